// round 10
// baseline (speedup 1.0000x reference)
#include <cuda_runtime.h>
#include <cuda_bf16.h>
#include <math.h>
#include <stdint.h>

#define BATCH 2048
#define SEQ   128
#define HID   512
#define TOUT  24
#define NTHR  512
#define GRID  128
#define NKT   32

// ---- global scratch (device globals: allocation-free, graph-safe) ----
__device__ uint4 g_Bpk[2][8][NKT][8][32];    // [enc/dec][slice][kt][ntl][lane]  2MB
__device__ uint4 g_A[16][2][8][NKT][2][32];  // [grp][plane][mt][kt][hi/lo][lane] 8MB
__device__ float g_xT[SEQ][BATCH];           // transposed input, 1MB
__device__ float g_part[16][8][128];         // fc partials
__device__ unsigned g_bar[16][32];           // group barrier counters
__device__ unsigned g_rst[16][32];           // reset counters

// ---- SMEM layout (bytes) ----
#define OFF_B    0         // resident B slice: 32kt x 8ntl x 32 x 16B = 131072
#define OFF_RING 131072    // A ring: 16w x 4slots x 1KB = 65536
#define OFF_EPE  196608    // 32 float4
#define OFF_EPD  197120    // 32 float4
#define OFF_FC2  197632    // 32 float2
#define OFF_DINP 197888    // 128 f
#define OFF_RED  198400    // 256 f
#define SMEM_SZ  199424

__device__ __forceinline__ uint32_t smem_u32(const void* p) {
    uint32_t a;
    asm("{ .reg .u64 t; cvta.to.shared.u64 t, %1; cvt.u32.u64 %0, t; }" : "=r"(a) : "l"(p));
    return a;
}
__device__ __forceinline__ void cpasync16(uint32_t dst, const void* src) {
    asm volatile("cp.async.cg.shared.global [%0], [%1], 16;" :: "r"(dst), "l"(src) : "memory");
}
__device__ __forceinline__ void cp_commit() { asm volatile("cp.async.commit_group;" ::: "memory"); }
__device__ __forceinline__ void cp_wait3()  { asm volatile("cp.async.wait_group 3;" ::: "memory"); }
__device__ __forceinline__ void cp_wait2()  { asm volatile("cp.async.wait_group 2;" ::: "memory"); }
__device__ __forceinline__ void cp_wait1()  { asm volatile("cp.async.wait_group 1;" ::: "memory"); }
__device__ __forceinline__ void cp_wait0()  { asm volatile("cp.async.wait_group 0;" ::: "memory"); }
__device__ __forceinline__ void mma_bf16(float* d,
                                         uint32_t a0, uint32_t a1, uint32_t a2, uint32_t a3,
                                         uint32_t b0, uint32_t b1) {
    asm volatile(
        "mma.sync.aligned.m16n8k16.row.col.f32.bf16.bf16.f32 "
        "{%0,%1,%2,%3}, {%4,%5,%6,%7}, {%8,%9}, {%0,%1,%2,%3};"
        : "+f"(d[0]), "+f"(d[1]), "+f"(d[2]), "+f"(d[3])
        : "r"(a0), "r"(a1), "r"(a2), "r"(a3), "r"(b0), "r"(b1));
}
__device__ __forceinline__ uint32_t pack_bf2(__nv_bfloat16 a, __nv_bfloat16 b) {
    __nv_bfloat162 t; t.x = a; t.y = b;
    return *reinterpret_cast<uint32_t*>(&t);
}
__device__ __forceinline__ void split2(float a, float b, uint32_t& hi, uint32_t& lo) {
    __nv_bfloat16 ah = __float2bfloat16(a);
    __nv_bfloat16 bh = __float2bfloat16(b);
    __nv_bfloat16 al = __float2bfloat16(a - __bfloat162float(ah));
    __nv_bfloat16 bl = __float2bfloat16(b - __bfloat162float(bh));
    hi = pack_bf2(ah, bh);
    lo = pack_bf2(al, bl);
}

// Prologue 1: pack Whh into fragment-ordered bf16 hi/lo (per N-slice layout).
__global__ void pack_b(const float* __restrict__ eW, const float* __restrict__ dW) {
    int e = blockIdx.x * 256 + threadIdx.x;          // 0..65535
    const float* W = blockIdx.y ? dW : eW;
    uint4* dst = &g_Bpk[blockIdx.y][0][0][0][0];
    int lane = e & 31, ntl = (e >> 5) & 7, kt = (e >> 8) & 31, sl = e >> 13;
    int n = sl * 64 + ntl * 8 + (lane >> 2);
    int k = kt * 16 + 2 * (lane & 3);
    const float* r = W + n * HID + k;
    uint32_t b0h, b0l, b1h, b1l;
    split2(r[0], r[1], b0h, b0l);
    split2(r[8], r[9], b1h, b1l);
    dst[((sl * NKT + kt) * 8 + ntl) * 32 + lane] = make_uint4(b0h, b1h, b0l, b1l);
}

// Prologue 2: transpose x -> g_xT[s][b].
__global__ void transpose_x(const float* __restrict__ x) {
    __shared__ float tile[32][33];
    int bx = blockIdx.x * 32, sx = blockIdx.y * 32;
    int tx = threadIdx.x, ty = threadIdx.y;
    #pragma unroll
    for (int i = 0; i < 32; i += 8)
        tile[ty + i][tx] = x[(bx + ty + i) * SEQ + sx + tx];
    __syncthreads();
    #pragma unroll
    for (int i = 0; i < 32; i += 8)
        g_xT[sx + ty + i][bx + tx] = tile[tx][ty + i];
}

__global__ __launch_bounds__(NTHR, 1)
void rnn_kernel(const float* __restrict__ eWih,
                const float* __restrict__ ebih, const float* __restrict__ ebhh,
                const float* __restrict__ dWih,
                const float* __restrict__ dbih, const float* __restrict__ dbhh,
                const float* __restrict__ fcW, const float* __restrict__ fcb,
                float* __restrict__ out)
{
    extern __shared__ char smem[];
    const int tid  = threadIdx.x;
    const int wid  = tid >> 5, lane = tid & 31;
    const int gid  = lane >> 2, tig = lane & 3;
    const int g    = blockIdx.x >> 3, s = blockIdx.x & 7;
    const int b0   = g * 128, n0 = s * 64, s4 = s * 4;
    const int mt   = wid & 7, nh = wid >> 3;
    const int r0   = mt * 16 + gid, r1 = r0 + 8;

    const uint4* smB   = (const uint4*)(smem + OFF_B);
    const uint32_t smB_u = smem_u32(smem + OFF_B);
    const uint4* ring  = (const uint4*)(smem + OFF_RING);
    const uint32_t ring_u = smem_u32(smem + OFF_RING);
    float4* epE  = (float4*)(smem + OFF_EPE);
    float4* epD  = (float4*)(smem + OFF_EPD);
    float2* fc2  = (float2*)(smem + OFF_FC2);
    float*  dinp = (float*)(smem + OFF_DINP);
    float*  red  = (float*)(smem + OFF_RED);

    // ---- epilogue tables for this CTA's 64 columns ----
    if (tid < 32) {
        int c0 = n0 + 2 * tid, c1 = c0 + 1;
        epE[tid] = make_float4(eWih[c0], eWih[c1],
                               ebih[c0] + ebhh[c0], ebih[c1] + ebhh[c1]);
        epD[tid] = make_float4(dWih[c0], dWih[c1],
                               dbih[c0] + dbhh[c0], dbih[c1] + dbhh[c1]);
        fc2[tid] = make_float2(fcW[c0], fcW[c1]);
    }
    const float fcb0 = fcb[0];

    // ---- resident encoder B load (once) ----
    {
        const uint4* bsrc = &g_Bpk[0][s][0][0][0];
        for (int i = tid; i < 8192; i += NTHR)
            cpasync16(smB_u + i * 16, bsrc + i);
        cp_commit();
    }
    // ---- zero A plane 0 (this CTA zeroes mt == s partition) ----
    {
        uint4* az = &g_A[g][0][s][0][0][0];
        for (int i = tid; i < 2048; i += NTHR) az[i] = make_uint4(0, 0, 0, 0);
    }
    cp_wait0();
    __syncthreads();

    unsigned ph = 0;
    auto gbar = [&]() {
        ph++;
        __threadfence();
        __syncthreads();
        if (tid == 0) {
            atomicAdd(&g_bar[g][0], 1u);
            unsigned v;
            do { v = atomicAdd(&g_bar[g][0], 0u); } while (v < 8u * ph);
        }
        __syncthreads();
    };

    // stage A fragment chunk (plane pl, k-tile kt) for this warp's mt into ring slot.
    auto stage = [&](int pl, int kt, int slot) {
        const uint4* src = &g_A[g][pl][mt][kt][0][lane];
        uint32_t d = ring_u + wid * 4096 + slot * 1024 + lane * 16;
        cpasync16(d, src);              // hi
        cpasync16(d + 512, src + 32);   // lo
        cp_commit();
    };
    auto prime = [&](int pl) {
        stage(pl, s4 + 0, 0);
        stage(pl, s4 + 1, 1);
        stage(pl, s4 + 2, 2);
    };

    gbar();      // zeros visible group-wide
    prime(0);

    float acc[4][4];
    auto consume = [&](int kt, int slot) {
        const uint4* rp = ring + wid * 256 + slot * 64;
        uint4 ah = rp[lane];
        uint4 al = rp[32 + lane];
        const uint4* bp = smB + (kt * 8 + nh * 4) * 32 + lane;
        uint4 bq0 = bp[0], bq1 = bp[32], bq2 = bp[64], bq3 = bp[96];
        // three terms, accumulators interleaved to break RAW chains
        mma_bf16(acc[0], ah.x, ah.y, ah.z, ah.w, bq0.x, bq0.y);
        mma_bf16(acc[1], ah.x, ah.y, ah.z, ah.w, bq1.x, bq1.y);
        mma_bf16(acc[2], ah.x, ah.y, ah.z, ah.w, bq2.x, bq2.y);
        mma_bf16(acc[3], ah.x, ah.y, ah.z, ah.w, bq3.x, bq3.y);
        mma_bf16(acc[0], al.x, al.y, al.z, al.w, bq0.x, bq0.y);
        mma_bf16(acc[1], al.x, al.y, al.z, al.w, bq1.x, bq1.y);
        mma_bf16(acc[2], al.x, al.y, al.z, al.w, bq2.x, bq2.y);
        mma_bf16(acc[3], al.x, al.y, al.z, al.w, bq3.x, bq3.y);
        mma_bf16(acc[0], ah.x, ah.y, ah.z, ah.w, bq0.z, bq0.w);
        mma_bf16(acc[1], ah.x, ah.y, ah.z, ah.w, bq1.z, bq1.w);
        mma_bf16(acc[2], ah.x, ah.y, ah.z, ah.w, bq2.z, bq2.w);
        mma_bf16(acc[3], ah.x, ah.y, ah.z, ah.w, bq3.z, bq3.w);
    };

    auto kloop = [&](int pl) {
        #pragma unroll
        for (int i = 0; i < 4; i++)
            #pragma unroll
            for (int j = 0; j < 4; j++) acc[i][j] = 0.f;
        #pragma unroll 1
        for (int idx = 0; idx < 29; idx++) {
            stage(pl, (s4 + idx + 3) & (NKT - 1), (idx + 3) & 3);
            cp_wait3();
            consume((s4 + idx) & (NKT - 1), idx & 3);
        }
        cp_wait2(); consume((s4 + 29) & (NKT - 1), 1);
        cp_wait1(); consume((s4 + 30) & (NKT - 1), 2);
        cp_wait0(); consume((s4 + 31) & (NKT - 1), 3);
    };

    // epilogue: h_new = tanh(acc + xv*wih + bias); write A fragments (plane np);
    // if dec, accumulate fc partials into red.
    auto epi = [&](float xv0, float xv1, const float4* __restrict__ ep, int np, bool dec) {
        uint32_t hiP[2][4], loP[2][4];
        float p0 = 0.f, p1 = 0.f;
        #pragma unroll
        for (int i = 0; i < 4; i++) {
            int pp = 16 * nh + 4 * i + tig;
            float4 co = ep[pp];
            float h00 = tanhf(acc[i][0] + xv0 * co.x + co.z);
            float h01 = tanhf(acc[i][1] + xv0 * co.y + co.w);
            float h10 = tanhf(acc[i][2] + xv1 * co.x + co.z);
            float h11 = tanhf(acc[i][3] + xv1 * co.y + co.w);
            if (dec) {
                float2 f = fc2[pp];
                p0 = fmaf(h00, f.x, fmaf(h01, f.y, p0));
                p1 = fmaf(h10, f.x, fmaf(h11, f.y, p1));
            }
            int half = i >> 1, sl = (i & 1) * 2;
            split2(h00, h01, hiP[half][sl],     loP[half][sl]);
            split2(h10, h11, hiP[half][sl + 1], loP[half][sl + 1]);
        }
        #pragma unroll
        for (int half = 0; half < 2; half++) {
            int kt = s4 + nh * 2 + half;
            g_A[g][np][mt][kt][0][lane] = make_uint4(hiP[half][0], hiP[half][1], hiP[half][2], hiP[half][3]);
            g_A[g][np][mt][kt][1][lane] = make_uint4(loP[half][0], loP[half][1], loP[half][2], loP[half][3]);
        }
        if (dec) {
            p0 += __shfl_xor_sync(0xffffffffu, p0, 1);
            p0 += __shfl_xor_sync(0xffffffffu, p0, 2);
            p1 += __shfl_xor_sync(0xffffffffu, p1, 1);
            p1 += __shfl_xor_sync(0xffffffffu, p1, 2);
            if (tig == 0) {
                red[nh * 128 + r0] = p0;
                red[nh * 128 + r1] = p1;
            }
        }
    };

    // ---- encoder: 128 steps ----
    #pragma unroll 1
    for (int t = 0; t < SEQ; t++) {
        const int pl = t & 1;
        float xv0 = __ldg(&g_xT[t][b0 + r0]);
        float xv1 = __ldg(&g_xT[t][b0 + r1]);
        kloop(pl);
        epi(xv0, xv1, epE, 1 - pl, false);
        __threadfence();       // own A STGs -> L2 (for self-prime)
        __syncthreads();       // all warps' epi done
        prime(1 - pl);         // own-CTA fragments: visible without gbar
        gbar();                // others' A fragments visible
    }

    // ---- swap to decoder B + init feedback input ----
    cp_wait0();
    __syncthreads();
    {
        const uint4* bsrc = &g_Bpk[1][s][0][0][0];
        for (int i = tid; i < 8192; i += NTHR)
            cpasync16(smB_u + i * 16, bsrc + i);
        cp_commit();
    }
    if (tid < 128) dinp[tid] = __ldg(&g_xT[SEQ - 1][b0 + tid]);
    cp_wait0();
    __syncthreads();
    prime(0);

    // ---- decoder: 24 steps ----
    #pragma unroll 1
    for (int t = 0; t < TOUT; t++) {
        const int pl = t & 1;
        float xv0 = dinp[r0];
        float xv1 = dinp[r1];
        kloop(pl);
        epi(xv0, xv1, epD, 1 - pl, true);
        __threadfence();
        __syncthreads();
        if (tid < 128)
            g_part[g][s][tid] = red[tid] + red[128 + tid];
        prime(1 - pl);
        gbar();
        if (tid < 128) {
            float o = fcb0;
            #pragma unroll
            for (int s2 = 0; s2 < 8; s2++)
                o += __ldcg(&g_part[g][s2][tid]);
            dinp[tid] = o;
            if (s == 0) out[(b0 + tid) * TOUT + t] = o;
        }
        __syncthreads();
    }

    // ---- drain + reset barrier counters for next graph replay ----
    cp_wait0();
    __syncthreads();
    if (tid == 0) {
        unsigned r = atomicAdd(&g_rst[g][0], 1u);
        if (r == 7u) {
            g_bar[g][0] = 0u;
            g_rst[g][0] = 0u;
            __threadfence();
        }
    }
}

extern "C" void kernel_launch(void* const* d_in, const int* in_sizes, int n_in,
                              void* d_out, int out_size) {
    (void)in_sizes; (void)n_in; (void)out_size;
    const float* x    = (const float*)d_in[0];
    const float* eWih = (const float*)d_in[1];
    const float* eWhh = (const float*)d_in[2];
    const float* ebih = (const float*)d_in[3];
    const float* ebhh = (const float*)d_in[4];
    const float* dWih = (const float*)d_in[5];
    const float* dWhh = (const float*)d_in[6];
    const float* dbih = (const float*)d_in[7];
    const float* dbhh = (const float*)d_in[8];
    const float* fcW  = (const float*)d_in[9];
    const float* fcb  = (const float*)d_in[10];

    cudaFuncSetAttribute(rnn_kernel, cudaFuncAttributeMaxDynamicSharedMemorySize, SMEM_SZ);

    pack_b<<<dim3(256, 2), 256>>>(eWhh, dWhh);
    transpose_x<<<dim3(BATCH / 32, SEQ / 32), dim3(32, 8)>>>(x);
    rnn_kernel<<<GRID, NTHR, SMEM_SZ>>>(eWih, ebih, ebhh,
                                        dWih, dbih, dbhh,
                                        fcW, fcb, (float*)d_out);
}

// round 11
// speedup vs baseline: 1.0412x; 1.0412x over previous
#include <cuda_runtime.h>
#include <cuda_bf16.h>
#include <math.h>
#include <stdint.h>

#define BATCH 2048
#define SEQ   128
#define HID   512
#define TOUT  24
#define NTHR  512
#define GRID  128
#define NKT   32

// ---- global scratch (device globals: allocation-free, graph-safe) ----
__device__ uint4 g_Bpk[2][8][NKT][8][32];    // [enc/dec][slice][kt][ntl][lane]  2MB
__device__ uint4 g_A[16][2][8][NKT][2][32];  // [grp][plane][mt][kt][hi/lo][lane] 8MB
__device__ float g_xT[SEQ][BATCH];           // transposed input
__device__ float g_part[2][16][8][128];      // fc partials (parity-buffered)
__device__ unsigned g_bar[16][32];           // group barrier counters
__device__ unsigned g_rst[16][32];           // reset counters

// ---- SMEM layout (bytes) ----
#define OFF_B    0         // resident B slice: 32kt x 8ntl x 32 x 16B = 131072
#define OFF_RING 131072    // A ring: 16w x 4slots x 1KB = 65536
#define OFF_EPE  196608    // 32 float4
#define OFF_EPD  197120    // 32 float4
#define OFF_FC2  197632    // 32 float2
#define OFF_DINP 197888    // 128 f
#define OFF_RED  198400    // 256 f
#define SMEM_SZ  199424

__device__ __forceinline__ uint32_t smem_u32(const void* p) {
    uint32_t a;
    asm("{ .reg .u64 t; cvta.to.shared.u64 t, %1; cvt.u32.u64 %0, t; }" : "=r"(a) : "l"(p));
    return a;
}
__device__ __forceinline__ void cpasync16(uint32_t dst, const void* src) {
    asm volatile("cp.async.cg.shared.global [%0], [%1], 16;" :: "r"(dst), "l"(src) : "memory");
}
__device__ __forceinline__ void cp_commit() { asm volatile("cp.async.commit_group;" ::: "memory"); }
__device__ __forceinline__ void cp_wait3()  { asm volatile("cp.async.wait_group 3;" ::: "memory"); }
__device__ __forceinline__ void cp_wait2()  { asm volatile("cp.async.wait_group 2;" ::: "memory"); }
__device__ __forceinline__ void cp_wait1()  { asm volatile("cp.async.wait_group 1;" ::: "memory"); }
__device__ __forceinline__ void cp_wait0()  { asm volatile("cp.async.wait_group 0;" ::: "memory"); }
__device__ __forceinline__ void mma_bf16(float* d,
                                         uint32_t a0, uint32_t a1, uint32_t a2, uint32_t a3,
                                         uint32_t b0, uint32_t b1) {
    asm volatile(
        "mma.sync.aligned.m16n8k16.row.col.f32.bf16.bf16.f32 "
        "{%0,%1,%2,%3}, {%4,%5,%6,%7}, {%8,%9}, {%0,%1,%2,%3};"
        : "+f"(d[0]), "+f"(d[1]), "+f"(d[2]), "+f"(d[3])
        : "r"(a0), "r"(a1), "r"(a2), "r"(a3), "r"(b0), "r"(b1));
}
__device__ __forceinline__ uint32_t pack_bf2(__nv_bfloat16 a, __nv_bfloat16 b) {
    __nv_bfloat162 t; t.x = a; t.y = b;
    return *reinterpret_cast<uint32_t*>(&t);
}
__device__ __forceinline__ void split2(float a, float b, uint32_t& hi, uint32_t& lo) {
    __nv_bfloat16 ah = __float2bfloat16(a);
    __nv_bfloat16 bh = __float2bfloat16(b);
    __nv_bfloat16 al = __float2bfloat16(a - __bfloat162float(ah));
    __nv_bfloat16 bl = __float2bfloat16(b - __bfloat162float(bh));
    hi = pack_bf2(ah, bh);
    lo = pack_bf2(al, bl);
}

// Prologue 1: pack Whh into fragment-ordered bf16 hi/lo (per N-slice layout).
__global__ void pack_b(const float* __restrict__ eW, const float* __restrict__ dW) {
    int e = blockIdx.x * 256 + threadIdx.x;
    const float* W = blockIdx.y ? dW : eW;
    uint4* dst = &g_Bpk[blockIdx.y][0][0][0][0];
    int lane = e & 31, ntl = (e >> 5) & 7, kt = (e >> 8) & 31, sl = e >> 13;
    int n = sl * 64 + ntl * 8 + (lane >> 2);
    int k = kt * 16 + 2 * (lane & 3);
    const float* r = W + n * HID + k;
    uint32_t b0h, b0l, b1h, b1l;
    split2(r[0], r[1], b0h, b0l);
    split2(r[8], r[9], b1h, b1l);
    dst[((sl * NKT + kt) * 8 + ntl) * 32 + lane] = make_uint4(b0h, b1h, b0l, b1l);
}

// Prologue 2: transpose x -> g_xT[s][b].
__global__ void transpose_x(const float* __restrict__ x) {
    __shared__ float tile[32][33];
    int bx = blockIdx.x * 32, sx = blockIdx.y * 32;
    int tx = threadIdx.x, ty = threadIdx.y;
    #pragma unroll
    for (int i = 0; i < 32; i += 8)
        tile[ty + i][tx] = x[(bx + ty + i) * SEQ + sx + tx];
    __syncthreads();
    #pragma unroll
    for (int i = 0; i < 32; i += 8)
        g_xT[sx + ty + i][bx + tx] = tile[tx][ty + i];
}

__global__ __launch_bounds__(NTHR, 1)
void rnn_kernel(const float* __restrict__ eWih,
                const float* __restrict__ ebih, const float* __restrict__ ebhh,
                const float* __restrict__ dWih,
                const float* __restrict__ dbih, const float* __restrict__ dbhh,
                const float* __restrict__ fcW, const float* __restrict__ fcb,
                float* __restrict__ out)
{
    extern __shared__ char smem[];
    const int tid  = threadIdx.x;
    const int wid  = tid >> 5, lane = tid & 31;
    const int gid  = lane >> 2, tig = lane & 3;
    const int g    = blockIdx.x >> 3, s = blockIdx.x & 7;
    const int b0   = g * 128, n0 = s * 64, s4 = s * 4;
    const int mt   = wid & 7, nh = wid >> 3;
    const int r0   = mt * 16 + gid, r1 = r0 + 8;

    const uint4* smB      = (const uint4*)(smem + OFF_B);
    const uint32_t smB_u  = smem_u32(smem + OFF_B);
    const uint4* ring     = (const uint4*)(smem + OFF_RING);
    uint4*       ringw    = (uint4*)(smem + OFF_RING);
    const uint32_t ring_u = smem_u32(smem + OFF_RING);
    float4* epE  = (float4*)(smem + OFF_EPE);
    float4* epD  = (float4*)(smem + OFF_EPD);
    float2* fc2  = (float2*)(smem + OFF_FC2);
    float*  dinp = (float*)(smem + OFF_DINP);
    float*  red  = (float*)(smem + OFF_RED);

    // ---- epilogue tables ----
    if (tid < 32) {
        int c0 = n0 + 2 * tid, c1 = c0 + 1;
        epE[tid] = make_float4(eWih[c0], eWih[c1],
                               ebih[c0] + ebhh[c0], ebih[c1] + ebhh[c1]);
        epD[tid] = make_float4(dWih[c0], dWih[c1],
                               dbih[c0] + dbhh[c0], dbih[c1] + dbhh[c1]);
        fc2[tid] = make_float2(fcW[c0], fcW[c1]);
    }
    const float fcb0 = fcb[0];

    // ---- resident encoder B load ----
    {
        const uint4* bsrc = &g_Bpk[0][s][0][0][0];
        for (int i = tid; i < 8192; i += NTHR)
            cpasync16(smB_u + i * 16, bsrc + i);
        cp_commit();
    }
    // ---- zero own g_A plane-0 partition + whole local ring (h0 = 0) ----
    {
        uint4* az = &g_A[g][0][s][0][0][0];
        for (int i = tid; i < 2048; i += NTHR) az[i] = make_uint4(0, 0, 0, 0);
        for (int i = tid; i < 4096; i += NTHR) ringw[i] = make_uint4(0, 0, 0, 0);
    }
    cp_wait0();

    unsigned ph = 0;
    volatile unsigned* barp = &g_bar[g][0];

    // arrive: CTA-wide release of prior STGs, then leader bump (grid.sync pattern)
    auto arrive = [&]() {
        __syncthreads();
        if (tid == 0) {
            __threadfence();
            atomicAdd(&g_bar[g][0], 1u);
        }
    };
    // wait: per-warp lane-0 spin + acquire; overlapped by caller with own-tile work
    auto wait_flag = [&]() {
        ph++;
        const unsigned tgt = 8u * ph;
        if (lane == 0) {
            while (*barp < tgt) { }
            __threadfence();
        }
        __syncwarp();
    };

    arrive();   // publish zeros

    // stage foreign A tile (plane pl, k-tile kt) into ring slot (warp-private)
    auto stage = [&](int pl, int kt, int slot) {
        const uint4* src = &g_A[g][pl][mt][kt][0][lane];
        uint32_t d = ring_u + wid * 4096 + slot * 1024 + lane * 16;
        cpasync16(d, src);
        cpasync16(d + 512, src + 32);
        cp_commit();
    };

    float acc[4][4];
    auto consume = [&](int kt, int slot) {
        const uint4* rp = ring + wid * 256 + slot * 64;
        uint4 ah = rp[lane];
        uint4 al = rp[32 + lane];
        const uint4* bp = smB + (kt * 8 + nh * 4) * 32 + lane;
        uint4 bq0 = bp[0], bq1 = bp[32], bq2 = bp[64], bq3 = bp[96];
        mma_bf16(acc[0], ah.x, ah.y, ah.z, ah.w, bq0.x, bq0.y);
        mma_bf16(acc[1], ah.x, ah.y, ah.z, ah.w, bq1.x, bq1.y);
        mma_bf16(acc[2], ah.x, ah.y, ah.z, ah.w, bq2.x, bq2.y);
        mma_bf16(acc[3], ah.x, ah.y, ah.z, ah.w, bq3.x, bq3.y);
        mma_bf16(acc[0], al.x, al.y, al.z, al.w, bq0.x, bq0.y);
        mma_bf16(acc[1], al.x, al.y, al.z, al.w, bq1.x, bq1.y);
        mma_bf16(acc[2], al.x, al.y, al.z, al.w, bq2.x, bq2.y);
        mma_bf16(acc[3], al.x, al.y, al.z, al.w, bq3.x, bq3.y);
        mma_bf16(acc[0], ah.x, ah.y, ah.z, ah.w, bq0.z, bq0.w);
        mma_bf16(acc[1], ah.x, ah.y, ah.z, ah.w, bq1.z, bq1.w);
        mma_bf16(acc[2], ah.x, ah.y, ah.z, ah.w, bq2.z, bq2.w);
        mma_bf16(acc[3], ah.x, ah.y, ah.z, ah.w, bq3.z, bq3.w);
    };

    // kloop: slots 0..3 hold OWN tiles (kt s4..s4+3) written by previous epi.
    // Barrier wait overlapped with own-tile consumption; foreign tiles streamed
    // via depth-4 cp.async ring from g_A.
    auto kloop = [&](int pl) {
        #pragma unroll
        for (int i = 0; i < 4; i++)
            #pragma unroll
            for (int j = 0; j < 4; j++) acc[i][j] = 0.f;
        consume(s4, 0);
        wait_flag();                              // foreign plane-pl fragments now visible
        stage(pl, (s4 + 4) & 31, 0);
        consume(s4 + 1, 1);
        stage(pl, (s4 + 5) & 31, 1);
        consume(s4 + 2, 2);
        stage(pl, (s4 + 6) & 31, 2);
        consume(s4 + 3, 3);
        stage(pl, (s4 + 7) & 31, 3);
        #pragma unroll 1
        for (int idx = 4; idx < 28; idx++) {
            cp_wait3();
            consume((s4 + idx) & 31, idx & 3);
            stage(pl, (s4 + idx + 4) & 31, idx & 3);
        }
        cp_wait3(); consume((s4 + 28) & 31, 0);
        cp_wait2(); consume((s4 + 29) & 31, 1);
        cp_wait1(); consume((s4 + 30) & 31, 2);
        cp_wait0(); consume((s4 + 31) & 31, 3);
    };

    // epilogue: h_new = tanh(acc + xv*wih + bias); write fragments to g_A (plane np)
    // AND directly into the local ring slots of both warps sharing this mt.
    auto epi = [&](float xv0, float xv1, const float4* __restrict__ ep, int np, bool dec) {
        uint32_t hiP[2][4], loP[2][4];
        float p0 = 0.f, p1 = 0.f;
        #pragma unroll
        for (int i = 0; i < 4; i++) {
            int pp = 16 * nh + 4 * i + tig;
            float4 co = ep[pp];
            float h00 = tanhf(acc[i][0] + xv0 * co.x + co.z);
            float h01 = tanhf(acc[i][1] + xv0 * co.y + co.w);
            float h10 = tanhf(acc[i][2] + xv1 * co.x + co.z);
            float h11 = tanhf(acc[i][3] + xv1 * co.y + co.w);
            if (dec) {
                float2 f = fc2[pp];
                p0 = fmaf(h00, f.x, fmaf(h01, f.y, p0));
                p1 = fmaf(h10, f.x, fmaf(h11, f.y, p1));
            }
            int half = i >> 1, sl = (i & 1) * 2;
            split2(h00, h01, hiP[half][sl],     loP[half][sl]);
            split2(h10, h11, hiP[half][sl + 1], loP[half][sl + 1]);
        }
        #pragma unroll
        for (int half = 0; half < 2; half++) {
            int ktl = nh * 2 + half;              // local slot 0..3
            int kt  = s4 + ktl;
            uint4 hv = make_uint4(hiP[half][0], hiP[half][1], hiP[half][2], hiP[half][3]);
            uint4 lv = make_uint4(loP[half][0], loP[half][1], loP[half][2], loP[half][3]);
            g_A[g][np][mt][kt][0][lane] = hv;     // for foreign CTAs
            g_A[g][np][mt][kt][1][lane] = lv;
            uint4* rA = ringw + mt * 256 + ktl * 64 + lane;        // warp (nh=0, mt)
            uint4* rB = ringw + (mt + 8) * 256 + ktl * 64 + lane;  // warp (nh=1, mt)
            rA[0] = hv; rA[32] = lv;
            rB[0] = hv; rB[32] = lv;
        }
        if (dec) {
            p0 += __shfl_xor_sync(0xffffffffu, p0, 1);
            p0 += __shfl_xor_sync(0xffffffffu, p0, 2);
            p1 += __shfl_xor_sync(0xffffffffu, p1, 1);
            p1 += __shfl_xor_sync(0xffffffffu, p1, 2);
            if (tig == 0) {
                red[nh * 128 + r0] = p0;
                red[nh * 128 + r1] = p1;
            }
        }
    };

    // ---- encoder: 128 steps ----
    #pragma unroll 1
    for (int t = 0; t < SEQ; t++) {
        const int pl = t & 1;
        float xv0 = __ldg(&g_xT[t][b0 + r0]);
        float xv1 = __ldg(&g_xT[t][b0 + r1]);
        kloop(pl);
        __syncthreads();            // all ring consumes done before epi overwrites slots
        epi(xv0, xv1, epE, 1 - pl, false);
        arrive();                   // syncthreads + leader fence + bump
    }

    // ---- swap to decoder B + init feedback input ----
    __syncthreads();
    {
        const uint4* bsrc = &g_Bpk[1][s][0][0][0];
        for (int i = tid; i < 8192; i += NTHR)
            cpasync16(smB_u + i * 16, bsrc + i);
        cp_commit();
    }
    if (tid < 128) dinp[tid] = __ldg(&g_xT[SEQ - 1][b0 + tid]);
    cp_wait0();
    __syncthreads();

    // ---- decoder: 24 steps ----
    #pragma unroll 1
    for (int t = 0; t < TOUT; t++) {
        const int pl = t & 1;
        kloop(pl);                  // wait also publishes g_part of step t-1
        if (t > 0 && tid < 128) {
            float o = fcb0;
            #pragma unroll
            for (int s2 = 0; s2 < 8; s2++)
                o += __ldcg(&g_part[(t - 1) & 1][g][s2][tid]);
            dinp[tid] = o;
            if (s == 0) out[(b0 + tid) * TOUT + (t - 1)] = o;
        }
        __syncthreads();            // dinp stable; ring consumes done
        float xv0 = dinp[r0];
        float xv1 = dinp[r1];
        epi(xv0, xv1, epD, 1 - pl, true);
        __syncthreads();            // red visible
        if (tid < 128)
            g_part[t & 1][g][s][tid] = red[tid] + red[128 + tid];
        arrive();
    }

    // ---- final output column ----
    wait_flag();
    if (tid < 128 && s == 0) {
        float o = fcb0;
        #pragma unroll
        for (int s2 = 0; s2 < 8; s2++)
            o += __ldcg(&g_part[(TOUT - 1) & 1][g][s2][tid]);
        out[(b0 + tid) * TOUT + (TOUT - 1)] = o;
    }

    // ---- reset barrier counters for next graph replay ----
    __syncthreads();
    if (tid == 0) {
        unsigned r = atomicAdd(&g_rst[g][0], 1u);
        if (r == 7u) {
            g_bar[g][0] = 0u;
            g_rst[g][0] = 0u;
            __threadfence();
        }
    }
}

extern "C" void kernel_launch(void* const* d_in, const int* in_sizes, int n_in,
                              void* d_out, int out_size) {
    (void)in_sizes; (void)n_in; (void)out_size;
    const float* x    = (const float*)d_in[0];
    const float* eWih = (const float*)d_in[1];
    const float* eWhh = (const float*)d_in[2];
    const float* ebih = (const float*)d_in[3];
    const float* ebhh = (const float*)d_in[4];
    const float* dWih = (const float*)d_in[5];
    const float* dWhh = (const float*)d_in[6];
    const float* dbih = (const float*)d_in[7];
    const float* dbhh = (const float*)d_in[8];
    const float* fcW  = (const float*)d_in[9];
    const float* fcb  = (const float*)d_in[10];

    cudaFuncSetAttribute(rnn_kernel, cudaFuncAttributeMaxDynamicSharedMemorySize, SMEM_SZ);

    pack_b<<<dim3(256, 2), 256>>>(eWhh, dWhh);
    transpose_x<<<dim3(BATCH / 32, SEQ / 32), dim3(32, 8)>>>(x);
    rnn_kernel<<<GRID, NTHR, SMEM_SZ>>>(eWih, ebih, ebhh,
                                        dWih, dbih, dbhh,
                                        fcW, fcb, (float*)d_out);
}

// round 12
// speedup vs baseline: 1.1933x; 1.1461x over previous
#include <cuda_runtime.h>
#include <cuda_bf16.h>
#include <math.h>
#include <stdint.h>

#define BATCH 2048
#define SEQ   128
#define HID   512
#define TOUT  24
#define NTHR  256    // 8 warps, one per m-tile
#define GRID  128
#define NKT   32

// ---- global scratch (device globals: allocation-free, graph-safe) ----
__device__ uint4 g_Bpk[2][8][NKT][8][32];    // [enc/dec][slice][kt][ntl][lane]
__device__ uint4 g_A[16][2][8][NKT][2][32];  // [grp][plane][mt][kt][hi/lo][lane]
__device__ float g_xT[SEQ][BATCH];           // transposed input
__device__ float g_part[2][16][8][128];      // fc partials (parity-buffered)
__device__ unsigned g_bar[16][32];           // group barrier counters
__device__ unsigned g_rst[16][32];           // reset counters

// ---- SMEM layout (bytes) ----
#define OFF_B    0         // resident B slice: 32kt x 8ntl x 32 x 16B = 131072
#define OFF_EPE  131072    // 32 float4
#define OFF_EPD  131584    // 32 float4
#define OFF_FC2  132096    // 32 float2
#define OFF_DINP 132352    // 128 f
#define SMEM_SZ  132864

__device__ __forceinline__ uint32_t smem_u32(const void* p) {
    uint32_t a;
    asm("{ .reg .u64 t; cvta.to.shared.u64 t, %1; cvt.u32.u64 %0, t; }" : "=r"(a) : "l"(p));
    return a;
}
__device__ __forceinline__ void cpasync16(uint32_t dst, const void* src) {
    asm volatile("cp.async.cg.shared.global [%0], [%1], 16;" :: "r"(dst), "l"(src) : "memory");
}
__device__ __forceinline__ void cp_commit() { asm volatile("cp.async.commit_group;" ::: "memory"); }
__device__ __forceinline__ void cp_wait0()  { asm volatile("cp.async.wait_group 0;" ::: "memory"); }
__device__ __forceinline__ void mma_bf16(float* d, uint4 a, uint32_t b0, uint32_t b1) {
    asm volatile(
        "mma.sync.aligned.m16n8k16.row.col.f32.bf16.bf16.f32 "
        "{%0,%1,%2,%3}, {%4,%5,%6,%7}, {%8,%9}, {%0,%1,%2,%3};"
        : "+f"(d[0]), "+f"(d[1]), "+f"(d[2]), "+f"(d[3])
        : "r"(a.x), "r"(a.y), "r"(a.z), "r"(a.w), "r"(b0), "r"(b1));
}
__device__ __forceinline__ uint32_t pack_bf2(__nv_bfloat16 a, __nv_bfloat16 b) {
    __nv_bfloat162 t; t.x = a; t.y = b;
    return *reinterpret_cast<uint32_t*>(&t);
}
__device__ __forceinline__ void split2(float a, float b, uint32_t& hi, uint32_t& lo) {
    __nv_bfloat16 ah = __float2bfloat16(a);
    __nv_bfloat16 bh = __float2bfloat16(b);
    __nv_bfloat16 al = __float2bfloat16(a - __bfloat162float(ah));
    __nv_bfloat16 bl = __float2bfloat16(b - __bfloat162float(bh));
    hi = pack_bf2(ah, bh);
    lo = pack_bf2(al, bl);
}

// Prologue 1: pack Whh into fragment-ordered bf16 hi/lo (proven in R8-R10).
__global__ void pack_b(const float* __restrict__ eW, const float* __restrict__ dW) {
    int e = blockIdx.x * 256 + threadIdx.x;
    const float* W = blockIdx.y ? dW : eW;
    uint4* dst = &g_Bpk[blockIdx.y][0][0][0][0];
    int lane = e & 31, ntl = (e >> 5) & 7, kt = (e >> 8) & 31, sl = e >> 13;
    int n = sl * 64 + ntl * 8 + (lane >> 2);
    int k = kt * 16 + 2 * (lane & 3);
    const float* r = W + n * HID + k;
    uint32_t b0h, b0l, b1h, b1l;
    split2(r[0], r[1], b0h, b0l);
    split2(r[8], r[9], b1h, b1l);
    dst[((sl * NKT + kt) * 8 + ntl) * 32 + lane] = make_uint4(b0h, b1h, b0l, b1l);
}

// Prologue 2: transpose x -> g_xT[s][b].
__global__ void transpose_x(const float* __restrict__ x) {
    __shared__ float tile[32][33];
    int bx = blockIdx.x * 32, sx = blockIdx.y * 32;
    int tx = threadIdx.x, ty = threadIdx.y;
    #pragma unroll
    for (int i = 0; i < 32; i += 8)
        tile[ty + i][tx] = x[(bx + ty + i) * SEQ + sx + tx];
    __syncthreads();
    #pragma unroll
    for (int i = 0; i < 32; i += 8)
        g_xT[sx + ty + i][bx + tx] = tile[tx][ty + i];
}

__global__ __launch_bounds__(NTHR, 1)
void rnn_kernel(const float* __restrict__ eWih,
                const float* __restrict__ ebih, const float* __restrict__ ebhh,
                const float* __restrict__ dWih,
                const float* __restrict__ dbih, const float* __restrict__ dbhh,
                const float* __restrict__ fcW, const float* __restrict__ fcb,
                float* __restrict__ out)
{
    extern __shared__ char smem[];
    const int tid  = threadIdx.x;
    const int wid  = tid >> 5, lane = tid & 31;
    const int gid  = lane >> 2, tig = lane & 3;
    const int g    = blockIdx.x >> 3, s = blockIdx.x & 7;
    const int b0   = g * 128, n0 = s * 64, s4 = s * 4;
    const int mt   = wid;                  // one m-tile per warp
    const int r0   = mt * 16 + gid, r1 = r0 + 8;

    const uint4*   smB   = (const uint4*)(smem + OFF_B);
    const uint32_t smB_u = smem_u32(smem + OFF_B);
    float4* epE  = (float4*)(smem + OFF_EPE);
    float4* epD  = (float4*)(smem + OFF_EPD);
    float2* fc2  = (float2*)(smem + OFF_FC2);
    float*  dinp = (float*)(smem + OFF_DINP);

    // ---- epilogue tables ----
    if (tid < 32) {
        int c0 = n0 + 2 * tid, c1 = c0 + 1;
        epE[tid] = make_float4(eWih[c0], eWih[c1],
                               ebih[c0] + ebhh[c0], ebih[c1] + ebhh[c1]);
        epD[tid] = make_float4(dWih[c0], dWih[c1],
                               dbih[c0] + dbhh[c0], dbih[c1] + dbhh[c1]);
        fc2[tid] = make_float2(fcW[c0], fcW[c1]);
    }
    const float fcb0 = fcb[0];

    // ---- resident encoder B load + zero own g_A plane-0 partition ----
    {
        const uint4* bsrc = &g_Bpk[0][s][0][0][0];
        for (int i = tid; i < 8192; i += NTHR)
            cpasync16(smB_u + i * 16, bsrc + i);
        cp_commit();
        uint4* az = &g_A[g][0][s][0][0][0];
        for (int i = tid; i < 2048; i += NTHR) az[i] = make_uint4(0, 0, 0, 0);
    }
    cp_wait0();

    unsigned ph = 0;
    volatile unsigned* barp = &g_bar[g][0];
    auto arrive = [&]() {
        __syncthreads();
        if (tid == 0) {
            __threadfence();
            atomicAdd(&g_bar[g][0], 1u);
        }
    };
    auto wait_flag = [&]() {
        ph++;
        const unsigned tgt = 8u * ph;
        if (lane == 0) {
            while (*barp < tgt) { }
            __threadfence();
        }
        __syncwarp();
    };

    arrive();   // publish zeros

    // Own h fragments live in registers across steps (h0 = 0).
    uint4 own_h[4], own_l[4];
    #pragma unroll
    for (int i = 0; i < 4; i++) {
        own_h[i] = make_uint4(0, 0, 0, 0);
        own_l[i] = make_uint4(0, 0, 0, 0);
    }

    float acc[8][4];

    // consume one k-tile: 8 n-tiles x 3 terms; acc-interleaved for MMA ILP.
    auto consume = [&](int kt, uint4 ah, uint4 al) {
        const uint4* bp = smB + kt * 256 + lane;
        uint4 b0 = bp[0],   b1 = bp[32],  b2 = bp[64],  b3 = bp[96];
        uint4 b4 = bp[128], b5 = bp[160], b6 = bp[192], b7 = bp[224];
        mma_bf16(acc[0], ah, b0.x, b0.y); mma_bf16(acc[1], ah, b1.x, b1.y);
        mma_bf16(acc[2], ah, b2.x, b2.y); mma_bf16(acc[3], ah, b3.x, b3.y);
        mma_bf16(acc[4], ah, b4.x, b4.y); mma_bf16(acc[5], ah, b5.x, b5.y);
        mma_bf16(acc[6], ah, b6.x, b6.y); mma_bf16(acc[7], ah, b7.x, b7.y);
        mma_bf16(acc[0], al, b0.x, b0.y); mma_bf16(acc[1], al, b1.x, b1.y);
        mma_bf16(acc[2], al, b2.x, b2.y); mma_bf16(acc[3], al, b3.x, b3.y);
        mma_bf16(acc[4], al, b4.x, b4.y); mma_bf16(acc[5], al, b5.x, b5.y);
        mma_bf16(acc[6], al, b6.x, b6.y); mma_bf16(acc[7], al, b7.x, b7.y);
        mma_bf16(acc[0], ah, b0.z, b0.w); mma_bf16(acc[1], ah, b1.z, b1.w);
        mma_bf16(acc[2], ah, b2.z, b2.w); mma_bf16(acc[3], ah, b3.z, b3.w);
        mma_bf16(acc[4], ah, b4.z, b4.w); mma_bf16(acc[5], ah, b5.z, b5.w);
        mma_bf16(acc[6], ah, b6.z, b6.w); mma_bf16(acc[7], ah, b7.z, b7.w);
    };

    // kloop: own 4 tiles from regs (overlaps the barrier), then 28 foreign
    // tiles via depth-4 __ldcg register pipeline (L1-bypass: planes recycle).
    auto kloop = [&](const uint4* __restrict__ base) {
        #pragma unroll
        for (int i = 0; i < 8; i++)
            #pragma unroll
            for (int j = 0; j < 4; j++) acc[i][j] = 0.f;
        consume(s4 + 0, own_h[0], own_l[0]);
        consume(s4 + 1, own_h[1], own_l[1]);
        consume(s4 + 2, own_h[2], own_l[2]);
        consume(s4 + 3, own_h[3], own_l[3]);
        wait_flag();
        uint4 ph_[4], pl_[4];
        #pragma unroll
        for (int u = 0; u < 4; u++) {
            int kt = (s4 + 4 + u) & 31;
            ph_[u] = __ldcg(base + kt * 64 + lane);
            pl_[u] = __ldcg(base + kt * 64 + 32 + lane);
        }
        #pragma unroll 1
        for (int j = 0; j < 6; j++) {
            #pragma unroll
            for (int u = 0; u < 4; u++) {
                int idx = 4 + j * 4 + u;
                int kt = (s4 + idx) & 31;
                uint4 ah = ph_[u], al = pl_[u];
                int nk = (s4 + idx + 4) & 31;
                ph_[u] = __ldcg(base + nk * 64 + lane);
                pl_[u] = __ldcg(base + nk * 64 + 32 + lane);
                consume(kt, ah, al);
            }
        }
        #pragma unroll
        for (int u = 0; u < 4; u++)
            consume((s4 + 28 + u) & 31, ph_[u], pl_[u]);
    };

    // epilogue: h = tanh(acc + xv*wih + bias); own fragments -> regs + g_A.
    auto epi = [&](float xv0, float xv1, const float4* __restrict__ ep,
                   uint4* __restrict__ gAw, bool dec, int par) {
        float p0 = 0.f, p1 = 0.f;
        uint4 nh_[4], nl_[4];
        #pragma unroll
        for (int i = 0; i < 8; i++) {
            int pp = 4 * i + tig;
            float4 co = ep[pp];
            float h00 = tanhf(acc[i][0] + xv0 * co.x + co.z);
            float h01 = tanhf(acc[i][1] + xv0 * co.y + co.w);
            float h10 = tanhf(acc[i][2] + xv1 * co.x + co.z);
            float h11 = tanhf(acc[i][3] + xv1 * co.y + co.w);
            if (dec) {
                float2 f = fc2[pp];
                p0 = fmaf(h00, f.x, fmaf(h01, f.y, p0));
                p1 = fmaf(h10, f.x, fmaf(h11, f.y, p1));
            }
            int ktl = i >> 1;
            if ((i & 1) == 0) {
                split2(h00, h01, nh_[ktl].x, nl_[ktl].x);
                split2(h10, h11, nh_[ktl].y, nl_[ktl].y);
            } else {
                split2(h00, h01, nh_[ktl].z, nl_[ktl].z);
                split2(h10, h11, nh_[ktl].w, nl_[ktl].w);
            }
        }
        #pragma unroll
        for (int ktl = 0; ktl < 4; ktl++) {
            own_h[ktl] = nh_[ktl];
            own_l[ktl] = nl_[ktl];
            int kt = s4 + ktl;
            gAw[kt * 64 + lane]      = nh_[ktl];
            gAw[kt * 64 + 32 + lane] = nl_[ktl];
        }
        if (dec) {
            p0 += __shfl_xor_sync(0xffffffffu, p0, 1);
            p0 += __shfl_xor_sync(0xffffffffu, p0, 2);
            p1 += __shfl_xor_sync(0xffffffffu, p1, 1);
            p1 += __shfl_xor_sync(0xffffffffu, p1, 2);
            if (tig == 0) {
                g_part[par][g][s][r0] = p0;
                g_part[par][g][s][r1] = p1;
            }
        }
    };

    const uint4* gAr[2] = { &g_A[g][0][mt][0][0][0], &g_A[g][1][mt][0][0][0] };
    uint4*       gAw[2] = { &g_A[g][0][mt][0][0][0], &g_A[g][1][mt][0][0][0] };

    // ---- encoder: 128 steps ----
    #pragma unroll 1
    for (int t = 0; t < SEQ; t++) {
        const int pl = t & 1;
        float xv0 = __ldg(&g_xT[t][b0 + r0]);
        float xv1 = __ldg(&g_xT[t][b0 + r1]);
        kloop(gAr[pl]);
        epi(xv0, xv1, epE, gAw[1 - pl], false, 0);
        arrive();
    }

    // ---- swap to decoder B + init feedback input ----
    __syncthreads();
    {
        const uint4* bsrc = &g_Bpk[1][s][0][0][0];
        for (int i = tid; i < 8192; i += NTHR)
            cpasync16(smB_u + i * 16, bsrc + i);
        cp_commit();
    }
    if (tid < 128) dinp[tid] = __ldg(&g_xT[SEQ - 1][b0 + tid]);
    cp_wait0();
    __syncthreads();

    // ---- decoder: 24 steps ----
    #pragma unroll 1
    for (int t = 0; t < TOUT; t++) {
        const int pl = t & 1;
        kloop(gAr[pl]);                 // wait also publishes g_part of step t-1
        if (t > 0 && tid < 128) {
            float o = fcb0;
            #pragma unroll
            for (int s2 = 0; s2 < 8; s2++)
                o += __ldcg(&g_part[(t - 1) & 1][g][s2][tid]);
            dinp[tid] = o;
            if (s == 0) out[(b0 + tid) * TOUT + (t - 1)] = o;
        }
        __syncthreads();                // dinp stable before epi reads it
        float xv0 = dinp[r0];
        float xv1 = dinp[r1];
        epi(xv0, xv1, epD, gAw[1 - pl], true, t & 1);
        arrive();
    }

    // ---- final output column ----
    wait_flag();
    if (tid < 128 && s == 0) {
        float o = fcb0;
        #pragma unroll
        for (int s2 = 0; s2 < 8; s2++)
            o += __ldcg(&g_part[(TOUT - 1) & 1][g][s2][tid]);
        out[(b0 + tid) * TOUT + (TOUT - 1)] = o;
    }

    // ---- reset barrier counters for next graph replay ----
    __syncthreads();
    if (tid == 0) {
        unsigned r = atomicAdd(&g_rst[g][0], 1u);
        if (r == 7u) {
            g_bar[g][0] = 0u;
            g_rst[g][0] = 0u;
            __threadfence();
        }
    }
}

extern "C" void kernel_launch(void* const* d_in, const int* in_sizes, int n_in,
                              void* d_out, int out_size) {
    (void)in_sizes; (void)n_in; (void)out_size;
    const float* x    = (const float*)d_in[0];
    const float* eWih = (const float*)d_in[1];
    const float* eWhh = (const float*)d_in[2];
    const float* ebih = (const float*)d_in[3];
    const float* ebhh = (const float*)d_in[4];
    const float* dWih = (const float*)d_in[5];
    const float* dWhh = (const float*)d_in[6];
    const float* dbih = (const float*)d_in[7];
    const float* dbhh = (const float*)d_in[8];
    const float* fcW  = (const float*)d_in[9];
    const float* fcb  = (const float*)d_in[10];

    cudaFuncSetAttribute(rnn_kernel, cudaFuncAttributeMaxDynamicSharedMemorySize, SMEM_SZ);

    pack_b<<<dim3(256, 2), 256>>>(eWhh, dWhh);
    transpose_x<<<dim3(BATCH / 32, SEQ / 32), dim3(32, 8)>>>(x);
    rnn_kernel<<<GRID, NTHR, SMEM_SZ>>>(eWih, ebih, ebhh,
                                        dWih, dbih, dbhh,
                                        fcW, fcb, (float*)d_out);
}